// round 14
// baseline (speedup 1.0000x reference)
#include <cuda_runtime.h>
#include <cuda_fp16.h>
#include <mma.h>

using namespace nvcuda;

// Problem constants (fixed by setup_inputs)
#define BATCH 4
#define HDIM 256
#define WDIM 256
#define MTOT 262144            // B*H*W
#define NCH 256                // hidden channels
#define K1P 224                // conv1 K: 25 taps * 8 padded channels (125 real) -> 224 (mult of 32)
#define K2 2304                // conv2 K: 9 taps * 256 ch
#define K3 256                 // conv3 K (1x1)
#define N_IT 5

// ---------------- device scratch (static globals: no allocation allowed) ----------------
// All GEMM operands kept as exact fp16 (hi, lo) pairs: v = hi + lo to ~22 bits.
__device__ __half g_Fh [(size_t)MTOT * 8];       // features NHWC, C padded 5->8 (hi)
__device__ __half g_Fl [(size_t)MTOT * 8];       // (lo)
__device__ __half g_A1h[(size_t)MTOT * K1P];     // conv1 im2col hi
__device__ __half g_A1l[(size_t)MTOT * K1P];     // conv1 im2col lo
__device__ __half g_h1h[(size_t)MTOT * NCH];
__device__ __half g_h1l[(size_t)MTOT * NCH];
__device__ __half g_h2h[(size_t)MTOT * NCH];
__device__ __half g_h2l[(size_t)MTOT * NCH];
__device__ __half g_h3h[(size_t)MTOT * NCH];
__device__ __half g_h3l[(size_t)MTOT * NCH];
__device__ float  g_xp[MTOT];                    // current xp (fp32, feeds stencil)
__device__ __half g_W1h[K1P * NCH];              // weights transposed to [K, N], hi/lo
__device__ __half g_W1l[K1P * NCH];
__device__ __half g_W2h[K2  * NCH];
__device__ __half g_W2l[K2  * NCH];
__device__ __half g_W3h[K3  * NCH];
__device__ __half g_W3l[K3  * NCH];
__device__ float  g_w4c[9 * NCH];                // conv4 weights fp32, tap-major

__device__ __forceinline__ void split2(float v, __half& h, __half& l) {
    h = __float2half_rn(v);
    l = __float2half_rn(v - __half2float(h));
}

// ---------------- weight prep (runs once per launch; cheap) ----------------
__global__ void prep_weights(const float* __restrict__ w1, const float* __restrict__ w2,
                             const float* __restrict__ w3, const float* __restrict__ w4)
{
    int idx = blockIdx.x * blockDim.x + threadIdx.x;   // grid covers 2304*256 = 589824
    if (idx < K1P * NCH) {
        int k = idx >> 8, oc = idx & 255;
        int tap = k >> 3, c = k & 7;
        float v = 0.f;
        if (tap < 25 && c < 5) {
            int kh = tap / 5, kw = tap % 5;
            v = w1[oc * 125 + c * 25 + kh * 5 + kw];   // OIHW (256,5,5,5)
        }
        split2(v, g_W1h[idx], g_W1l[idx]);
    }
    if (idx < K2 * NCH) {
        int k = idx >> 8, oc = idx & 255;
        int tap = k >> 8, c = k & 255;
        split2(w2[oc * 2304 + c * 9 + tap], g_W2h[idx], g_W2l[idx]);  // OIHW (256,256,3,3)
    }
    if (idx < K3 * NCH) {
        int k = idx >> 8, oc = idx & 255;
        split2(w3[oc * 256 + k], g_W3h[idx], g_W3l[idx]);             // (256,256,1,1)
    }
    if (idx < 9 * NCH) {
        int tap = idx >> 8, c = idx & 255;
        g_w4c[idx] = w4[c * 9 + tap];                                 // (1,256,3,3)
    }
}

// ---------------- stencil features (fp32 math, hi/lo fp16 store) ----------------
__global__ void features_kernel(const float* __restrict__ x)
{
    int p = blockIdx.x * blockDim.x + threadIdx.x;
    int b = p >> 16, y = (p >> 8) & 255, xx = p & 255;
    int base = b << 16;
    float pc = g_xp[p];
    float c0 = 1.f, c1 = 0.f, c2 = 0.f, c3 = 0.f;
    int s = 0;
#pragma unroll
    for (int dy = -1; dy <= 1; dy++)
#pragma unroll
        for (int dx = -1; dx <= 1; dx++) {
            if (dy == 0 && dx == 0) continue;
            float q = g_xp[base | (((y + dy) & 255) << 8) | ((xx + dx) & 255)];
            if (q > 0.5f) s++;
            float r = 1.f - q;
            c3 = c3 * r + c2 * q;   // sequential DP, matches reference order
            c2 = c2 * r + c1 * q;
            c1 = c1 * r + c0 * q;
            c0 = c0 * r;
        }
    bool pb = pc > 0.5f;
    bool predb = (s == 3) || (pb && (s == 2));
    float xpred = c3 + c2 * pc;
    float xc = x[p];

    __half xh, xl, ph, pl, rh, rl;
    split2(xc, xh, xl);
    split2(pc, ph, pl);
    split2(xpred, rh, rl);
    __half one = __float2half_rn(1.f), zero = __float2half_rn(0.f);

    union { uint4 u; __half h[8]; } hk, lk;
    hk.h[0] = xh; hk.h[1] = ph; hk.h[2] = pb ? one : zero; hk.h[3] = rh;
    hk.h[4] = predb ? one : zero; hk.h[5] = zero; hk.h[6] = zero; hk.h[7] = zero;
    lk.h[0] = xl; lk.h[1] = pl; lk.h[2] = zero; lk.h[3] = rl;
    lk.h[4] = zero; lk.h[5] = zero; lk.h[6] = zero; lk.h[7] = zero;
    *(uint4*)(g_Fh + (size_t)p * 8) = hk.u;
    *(uint4*)(g_Fl + (size_t)p * 8) = lk.u;
}

// ---------------- conv1 im2col: A1[p][tap*8 + c], 28 taps (3 zero pad taps) ----------------
__global__ void im2col1_kernel()
{
    int idx = blockIdx.x * blockDim.x + threadIdx.x;   // MTOT*28 exactly
    int t = idx % 28;
    int p = idx / 28;
    uint4 vh = {0u, 0u, 0u, 0u}, vl = {0u, 0u, 0u, 0u};
    if (t < 25) {
        int kh = t / 5, kw = t % 5;
        int b = p >> 16, y = (p >> 8) & 255, xx = p & 255;
        int src = (b << 16) | (((y + kh - 2) & 255) << 8) | ((xx + kw - 2) & 255);
        vh = *(const uint4*)(g_Fh + (size_t)src * 8);
        vl = *(const uint4*)(g_Fl + (size_t)src * 8);
    }
    *(uint4*)(g_A1h + (size_t)p * K1P + t * 8) = vh;
    *(uint4*)(g_A1l + (size_t)p * K1P + t * 8) = vl;
}

// ---------------- 3xFP16 GEMM (wmma): C = relu(A @ Wt + bias) to ~fp32 accuracy ----------
// Three accumulation passes into the same fp32 accumulators:
//   pass0: A_hi * W_hi    pass1: A_hi * W_lo    pass2: A_lo * W_hi
// mode 0: A is plain row-major [M, K]
// mode 1: implicit 3x3 toroidal im2col over NHWC[256] input (K must be 2304)
// Output written as an exact fp16 (hi, lo) pair.
__global__ void gemm_kernel(const __half* __restrict__ Ah, const __half* __restrict__ Al,
                            const __half* __restrict__ Wh, const __half* __restrict__ Wl,
                            const float* __restrict__ bias,
                            __half* __restrict__ outh, __half* __restrict__ outl,
                            int K, int mode)
{
    __shared__ __align__(16) __half As[2][128][48];    // BM=128, BK=32, pad->48
    __shared__ __align__(16) __half Bs[2][32][136];    // BK=32, BN=128, pad->136

    int tid = threadIdx.x;
    int w = tid >> 5, lane = tid & 31;
    int w_m = w & 3, w_n = w >> 2;                     // 4 (M) x 2 (N) warps, warp tile 32x64
    int m0 = blockIdx.y * 128;
    int n0 = blockIdx.x * 128;
    int b_img = m0 >> 16;
    int y_img = (m0 >> 8) & 255;
    int x_img0 = m0 & 255;                             // M-tile is half an image row

    int aRow = tid >> 2, aQ = tid & 3;                 // A tile: 128x32 halves
    int bRow = tid >> 4, bQ = tid & 15;                // B tile: 32x128 halves

    wmma::fragment<wmma::accumulator, 16, 16, 16, float> acc[2][4];
#pragma unroll
    for (int i = 0; i < 2; i++)
#pragma unroll
        for (int j = 0; j < 4; j++) wmma::fill_fragment(acc[i][j], 0.f);

    int nk = K >> 5;
    int nk3 = nk * 3;
    uint4 ra[2], rb[2];

    const __half* Aps[3] = {Ah, Ah, Al};
    const __half* Wps[3] = {Wh, Wl, Wh};

    auto loadA = [&](int g, uint4* r) {
        int pass = (g >= 2 * nk) ? 2 : (g >= nk) ? 1 : 0;
        int k0 = (g - pass * nk) << 5;
        const __half* A = Aps[pass];
#pragma unroll
        for (int j = 0; j < 2; j++) {
            int row = aRow + 64 * j;
            const __half* src;
            if (mode == 0) {
                src = A + (size_t)(m0 + row) * K + k0 + aQ * 8;
            } else {
                int tap = k0 >> 8;                     // constant within k-tile (256%32==0)
                int dy = tap / 3 - 1, dx = tap % 3 - 1;
                int yy = (y_img + dy) & 255;
                int xs = (x_img0 + row + dx) & 255;
                int srcp = (b_img << 16) | (yy << 8) | xs;
                src = A + (size_t)srcp * 256 + (k0 & 255) + aQ * 8;
            }
            r[j] = *(const uint4*)src;
        }
    };
    auto loadB = [&](int g, uint4* r) {
        int pass = (g >= 2 * nk) ? 2 : (g >= nk) ? 1 : 0;
        int k0 = (g - pass * nk) << 5;
        const __half* Wt = Wps[pass];
#pragma unroll
        for (int j = 0; j < 2; j++)
            r[j] = *(const uint4*)(Wt + (size_t)(k0 + bRow + 16 * j) * 256 + n0 + bQ * 8);
    };
    auto storeTiles = [&](int buf, uint4* pa, uint4* pb) {
#pragma unroll
        for (int j = 0; j < 2; j++) {
            *(uint4*)&As[buf][aRow + 64 * j][aQ * 8] = pa[j];
            *(uint4*)&Bs[buf][bRow + 16 * j][bQ * 8] = pb[j];
        }
    };

    loadA(0, ra); loadB(0, rb);
    storeTiles(0, ra, rb);
    __syncthreads();

    for (int g = 0; g < nk3; ++g) {
        int cur = g & 1;
        if (g + 1 < nk3) { loadA(g + 1, ra); loadB(g + 1, rb); }
#pragma unroll
        for (int kk = 0; kk < 2; ++kk) {
            wmma::fragment<wmma::matrix_a, 16, 16, 16, __half, wmma::row_major> af[2];
            wmma::fragment<wmma::matrix_b, 16, 16, 16, __half, wmma::row_major> bf[4];
#pragma unroll
            for (int i = 0; i < 2; i++)
                wmma::load_matrix_sync(af[i], &As[cur][w_m * 32 + i * 16][kk * 16], 48);
#pragma unroll
            for (int j = 0; j < 4; j++)
                wmma::load_matrix_sync(bf[j], &Bs[cur][kk * 16][w_n * 64 + j * 16], 136);
#pragma unroll
            for (int i = 0; i < 2; i++)
#pragma unroll
                for (int j = 0; j < 4; j++)
                    wmma::mma_sync(acc[i][j], af[i], bf[j], acc[i][j]);
        }
        if (g + 1 < nk3) {
            __syncthreads();
            storeTiles((g + 1) & 1, ra, rb);
            __syncthreads();
        }
    }

    // epilogue: bias + relu + split fp16 (hi, lo) store
    __syncthreads();
    float* stage = ((float*)&As[0][0][0]) + w * 256;   // 1KB per warp
#pragma unroll
    for (int i = 0; i < 2; i++) {
#pragma unroll
        for (int j = 0; j < 4; j++) {
            wmma::store_matrix_sync(stage, acc[i][j], 16, wmma::mem_row_major);
            __syncwarp();
#pragma unroll
            for (int e = 0; e < 8; e++) {
                int idx = lane * 8 + e;
                int r = idx >> 4, c = idx & 15;
                int col = n0 + w_n * 64 + j * 16 + c;
                int grow = m0 + w_m * 32 + i * 16 + r;
                float v = fmaxf(stage[idx] + bias[col], 0.f);
                __half vh, vl;
                split2(v, vh, vl);
                outh[(size_t)grow * 256 + col] = vh;
                outl[(size_t)grow * 256 + col] = vl;
            }
            __syncwarp();
        }
    }
}

// ---------------- conv4 (3x3, 256->1) + sigmoid: warp per pixel, fp32 ----------------
__global__ void conv4_kernel(const float* __restrict__ b4, float* __restrict__ extra)
{
    __shared__ float sw[9 * NCH];
    for (int i = threadIdx.x; i < 9 * NCH; i += blockDim.x) sw[i] = g_w4c[i];
    __syncthreads();

    int gw = (blockIdx.x * blockDim.x + threadIdx.x) >> 5;   // pixel index
    int lane = threadIdx.x & 31;
    int b = gw >> 16, y = (gw >> 8) & 255, xx = gw & 255;
    float acc = 0.f;
#pragma unroll
    for (int tap = 0; tap < 9; tap++) {
        int dy = tap / 3 - 1, dx = tap % 3 - 1;
        int src = (b << 16) | (((y + dy) & 255) << 8) | ((xx + dx) & 255);
        union { uint4 u; __half2 h[4]; } vh, vl;
        vh.u = *(const uint4*)(g_h3h + (size_t)src * 256 + lane * 8);
        vl.u = *(const uint4*)(g_h3l + (size_t)src * 256 + lane * 8);
        const float* wt = sw + tap * 256 + lane * 8;
#pragma unroll
        for (int e = 0; e < 4; e++) {
            float2 fh = __half22float2(vh.h[e]);
            float2 fl = __half22float2(vl.h[e]);
            acc += (fh.x + fl.x) * wt[2 * e] + (fh.y + fl.y) * wt[2 * e + 1];
        }
    }
#pragma unroll
    for (int o = 16; o; o >>= 1) acc += __shfl_xor_sync(0xffffffffu, acc, o);
    if (lane == 0) {
        float r = 1.f / (1.f + expf(-(acc + b4[0])));
        g_xp[gw] = r;
        if (extra) extra[gw] = r;
    }
}

// ---------------- launch ----------------
extern "C" void kernel_launch(void* const* d_in, const int* in_sizes, int n_in,
                              void* d_out, int out_size)
{
    const float* x  = (const float*)d_in[0];
    const float* w1 = (const float*)d_in[1];
    const float* b1 = (const float*)d_in[2];
    const float* w2 = (const float*)d_in[3];
    const float* b2 = (const float*)d_in[4];
    const float* w3 = (const float*)d_in[5];
    const float* b3 = (const float*)d_in[6];
    const float* w4 = (const float*)d_in[7];
    const float* b4 = (const float*)d_in[8];
    float* out = (float*)d_out;

    void *pA1h, *pA1l, *ph1h, *ph1l, *ph2h, *ph2l, *ph3h, *ph3l;
    void *pW1h, *pW1l, *pW2h, *pW2l, *pW3h, *pW3l, *pxp;
    cudaGetSymbolAddress(&pA1h, g_A1h); cudaGetSymbolAddress(&pA1l, g_A1l);
    cudaGetSymbolAddress(&ph1h, g_h1h); cudaGetSymbolAddress(&ph1l, g_h1l);
    cudaGetSymbolAddress(&ph2h, g_h2h); cudaGetSymbolAddress(&ph2l, g_h2l);
    cudaGetSymbolAddress(&ph3h, g_h3h); cudaGetSymbolAddress(&ph3l, g_h3l);
    cudaGetSymbolAddress(&pW1h, g_W1h); cudaGetSymbolAddress(&pW1l, g_W1l);
    cudaGetSymbolAddress(&pW2h, g_W2h); cudaGetSymbolAddress(&pW2l, g_W2l);
    cudaGetSymbolAddress(&pW3h, g_W3h); cudaGetSymbolAddress(&pW3l, g_W3l);
    cudaGetSymbolAddress(&pxp, g_xp);

    // xp <- x
    cudaMemcpyAsync(pxp, x, (size_t)MTOT * sizeof(float), cudaMemcpyDeviceToDevice, 0);

    prep_weights<<<2304, 256>>>(w1, w2, w3, w4);

    dim3 ggrid(2, MTOT / 128);   // N/128 = 2, M/128 = 2048
    for (int it = 0; it < N_IT; ++it) {
        features_kernel<<<MTOT / 256, 256>>>(x);
        im2col1_kernel<<<(MTOT * 28) / 256, 256>>>();
        gemm_kernel<<<ggrid, 256>>>((const __half*)pA1h, (const __half*)pA1l,
                                    (const __half*)pW1h, (const __half*)pW1l, b1,
                                    (__half*)ph1h, (__half*)ph1l, K1P, 0);
        gemm_kernel<<<ggrid, 256>>>((const __half*)ph1h, (const __half*)ph1l,
                                    (const __half*)pW2h, (const __half*)pW2l, b2,
                                    (__half*)ph2h, (__half*)ph2l, K2, 1);
        gemm_kernel<<<ggrid, 256>>>((const __half*)ph2h, (const __half*)ph2l,
                                    (const __half*)pW3h, (const __half*)pW3l, b3,
                                    (__half*)ph3h, (__half*)ph3l, K3, 0);
        conv4_kernel<<<(MTOT * 32) / 256, 256>>>(b4, (it == N_IT - 1) ? out : nullptr);
    }
}

// round 17
// speedup vs baseline: 2.0485x; 2.0485x over previous
#include <cuda_runtime.h>
#include <cuda_fp16.h>
#include <mma.h>
#include <cstdint>

using namespace nvcuda;

// Problem constants (fixed by setup_inputs)
#define MTOT 262144            // B*H*W = 4*256*256
#define NCH 256
#define K1P 224                // conv1 K: 28 taps * 8 padded ch (25 real taps, 5 real ch)
#define K2 2304                // conv2 K: 9 taps * 256
#define K3 256                 // conv3 K
#define N_IT 5

// GEMM tiling
#define BM 128
#define BK 32
#define LDA 40                 // 80B rows: odd multiple of 16B -> conflict-free LDSM
#define LDB 136                // 272B rows: odd multiple of 16B
#define STAGES 4
#define A_STAGE (BM*LDA)       // halves per A stage (5120)
#define B_STAGE (BK*LDB)       // halves per B stage (4352)
#define SMEM_BYTES ((STAGES*(A_STAGE+B_STAGE))*2 + 512)   // 76288

// ---------------- device scratch (hi/lo exact fp16 pairs everywhere) ----------------
__device__ __align__(16) __half g_Fh [(size_t)MTOT * 8];
__device__ __align__(16) __half g_Fl [(size_t)MTOT * 8];
__device__ __align__(16) __half g_h1h[(size_t)MTOT * NCH];
__device__ __align__(16) __half g_h1l[(size_t)MTOT * NCH];
__device__ __align__(16) __half g_h2h[(size_t)MTOT * NCH];
__device__ __align__(16) __half g_h2l[(size_t)MTOT * NCH];
__device__ __align__(16) __half g_h3h[(size_t)MTOT * NCH];
__device__ __align__(16) __half g_h3l[(size_t)MTOT * NCH];
__device__ float  g_xp[MTOT];
__device__ __align__(16) __half g_W1h[K1P * NCH];
__device__ __align__(16) __half g_W1l[K1P * NCH];
__device__ __align__(16) __half g_W2h[K2  * NCH];
__device__ __align__(16) __half g_W2l[K2  * NCH];
__device__ __align__(16) __half g_W3h[K3  * NCH];
__device__ __align__(16) __half g_W3l[K3  * NCH];
__device__ float  g_w4c[9 * NCH];

__device__ __forceinline__ void split2(float v, __half& h, __half& l) {
    h = __float2half_rn(v);
    l = __float2half_rn(v - __half2float(h));
}

// ---------------- cp.async helpers ----------------
__device__ __forceinline__ void cp_async16(unsigned dst, const void* src, int srcsize) {
    asm volatile("cp.async.cg.shared.global [%0], [%1], 16, %2;\n"
                 :: "r"(dst), "l"(src), "r"(srcsize));
}
__device__ __forceinline__ void cp_commit() { asm volatile("cp.async.commit_group;\n"); }
template<int N> __device__ __forceinline__ void cp_wait() {
    asm volatile("cp.async.wait_group %0;\n" :: "n"(N));
}

// ---------------- weight prep ----------------
__global__ void prep_weights(const float* __restrict__ w1, const float* __restrict__ w2,
                             const float* __restrict__ w3, const float* __restrict__ w4)
{
    int idx = blockIdx.x * blockDim.x + threadIdx.x;   // covers 2304*256
    if (idx < K1P * NCH) {
        int k = idx >> 8, oc = idx & 255;
        int tap = k >> 3, c = k & 7;
        float v = 0.f;
        if (tap < 25 && c < 5) {
            int kh = tap / 5, kw = tap % 5;
            v = w1[oc * 125 + c * 25 + kh * 5 + kw];            // OIHW (256,5,5,5)
        }
        split2(v, g_W1h[idx], g_W1l[idx]);
    }
    if (idx < K2 * NCH) {
        int k = idx >> 8, oc = idx & 255;
        int tap = k >> 8, c = k & 255;
        split2(w2[oc * 2304 + c * 9 + tap], g_W2h[idx], g_W2l[idx]);
    }
    if (idx < K3 * NCH) {
        int k = idx >> 8, oc = idx & 255;
        split2(w3[oc * 256 + k], g_W3h[idx], g_W3l[idx]);
    }
    if (idx < 9 * NCH) {
        int tap = idx >> 8, c = idx & 255;
        g_w4c[idx] = w4[c * 9 + tap];
    }
}

// ---------------- stencil features (identical arithmetic to the passing R8 kernel) -------
__global__ void features_kernel(const float* __restrict__ x)
{
    int p = blockIdx.x * blockDim.x + threadIdx.x;
    int b = p >> 16, y = (p >> 8) & 255, xx = p & 255;
    int base = b << 16;
    float pc = g_xp[p];
    float c0 = 1.f, c1 = 0.f, c2 = 0.f, c3 = 0.f;
    int s = 0;
#pragma unroll
    for (int dy = -1; dy <= 1; dy++)
#pragma unroll
        for (int dx = -1; dx <= 1; dx++) {
            if (dy == 0 && dx == 0) continue;
            float q = g_xp[base | (((y + dy) & 255) << 8) | ((xx + dx) & 255)];
            if (q > 0.5f) s++;
            float r = 1.f - q;
            c3 = c3 * r + c2 * q;   // sequential DP, matches reference order
            c2 = c2 * r + c1 * q;
            c1 = c1 * r + c0 * q;
            c0 = c0 * r;
        }
    bool pb = pc > 0.5f;
    bool predb = (s == 3) || (pb && (s == 2));
    float xpred = c3 + c2 * pc;
    float xc = x[p];

    __half xh, xl, ph, pl, rh, rl;
    split2(xc, xh, xl);
    split2(pc, ph, pl);
    split2(xpred, rh, rl);
    __half one = __float2half_rn(1.f), zero = __float2half_rn(0.f);

    union { uint4 u; __half h[8]; } hk, lk;
    hk.h[0] = xh; hk.h[1] = ph; hk.h[2] = pb ? one : zero; hk.h[3] = rh;
    hk.h[4] = predb ? one : zero; hk.h[5] = zero; hk.h[6] = zero; hk.h[7] = zero;
    lk.h[0] = xl; lk.h[1] = pl; lk.h[2] = zero; lk.h[3] = rl;
    lk.h[4] = zero; lk.h[5] = zero; lk.h[6] = zero; lk.h[7] = zero;
    *(uint4*)(g_Fh + (size_t)p * 8) = hk.u;
    *(uint4*)(g_Fl + (size_t)p * 8) = lk.u;
}

// ---------------- 3xFP16 GEMM, PASS-MAJOR (bit-identical accumulation order to R8) -------
// g in [0, 3*nk): pass = g/nk (0: Ah*Wh, 1: Ah*Wl, 2: Al*Wh), kt = g%nk.
// Each stage holds exactly one A-plane tile + one W-plane tile.
// mode 0: A plain row-major [M, K]
// mode 1: implicit 3x3 toroidal im2col over NHWC[256]   (conv2, K=2304)
// mode 2: implicit 5x5 toroidal im2col over NHWC[8]     (conv1, K=224; one 16B chunk = one tap)
__global__ void __launch_bounds__(256, 2) gemm_kernel(
    const __half* __restrict__ Ah, const __half* __restrict__ Al,
    const __half* __restrict__ Wh, const __half* __restrict__ Wl,
    const float* __restrict__ bias,
    __half* __restrict__ outh, __half* __restrict__ outl,
    int K, int mode)
{
    extern __shared__ __align__(16) char smem_raw[];
    __half* sA = (__half*)smem_raw;
    __half* sB = sA + STAGES * A_STAGE;
    float*  sBias = (float*)(sB + STAGES * B_STAGE);

    const int tid = threadIdx.x;
    const int wid = tid >> 5, lane = tid & 31;
    const int w_m = wid & 3, w_n = wid >> 2;               // 4(M) x 2(N) warps, 32x64 tiles
    const int m0 = blockIdx.y * BM, n0 = blockIdx.x * 128;
    const int b_img = m0 >> 16, y_img = (m0 >> 8) & 255, x0 = m0 & 255;

    if (tid < 128) sBias[tid] = bias[n0 + tid];

    const unsigned uA = (unsigned)__cvta_generic_to_shared(sA);
    const unsigned uB = (unsigned)__cvta_generic_to_shared(sB);

    const int nk = K >> 5;
    const int nk3 = nk * 3;

    auto issue = [&](int g) {
        const int pass = (g >= 2 * nk) ? 2 : (g >= nk) ? 1 : 0;
        const int kt = g - pass * nk;
        const int s = g % STAGES;
        const int k0 = kt << 5;
        const __half* Asrc = (pass == 2) ? Al : Ah;
        const __half* Wsrc = (pass == 1) ? Wl : Wh;
        // A: 128x32 halves = 512 x 16B chunks; 2 per thread
#pragma unroll
        for (int h2 = 0; h2 < 2; h2++) {
            int t = tid + h2 * 256;
            int row = t >> 2, q = t & 3;
            const __half* src;
            int sz = 16;
            if (mode == 0) {
                src = Asrc + (size_t)(m0 + row) * K + k0 + q * 8;
            } else if (mode == 1) {
                int tap = k0 >> 8;                         // constant in k-tile (256%32==0)
                int dy = tap / 3 - 1, dx = tap % 3 - 1;
                int yy = (y_img + dy) & 255;
                int xs = (x0 + row + dx) & 255;
                src = Asrc + ((size_t)((b_img << 16) | (yy << 8) | xs)) * 256 + (k0 & 255) + q * 8;
            } else {
                int tap = (k0 >> 3) + q;                   // one 16B chunk = one tap's 8 ch
                int ok = (tap < 25);
                int tt = ok ? tap : 0;
                int dy = tt / 5 - 2, dx = tt % 5 - 2;
                int yy = (y_img + dy) & 255;
                int xs = (x0 + row + dx) & 255;
                src = Asrc + ((size_t)((b_img << 16) | (yy << 8) | xs)) * 8;
                sz = ok ? 16 : 0;                          // zero-fill pad taps
            }
            cp_async16(uA + (unsigned)(s * A_STAGE + row * LDA + q * 8) * 2u, src, sz);
        }
        // B: 32x128 halves = 512 x 16B chunks; 2 per thread
#pragma unroll
        for (int h2 = 0; h2 < 2; h2++) {
            int t = tid + h2 * 256;
            int row = t >> 4, q = t & 15;
            const __half* src = Wsrc + (size_t)(k0 + row) * 256 + n0 + q * 8;
            cp_async16(uB + (unsigned)(s * B_STAGE + row * LDB + q * 8) * 2u, src, 16);
        }
    };

    wmma::fragment<wmma::accumulator, 16, 16, 16, float> acc[2][4];
#pragma unroll
    for (int i = 0; i < 2; i++)
#pragma unroll
        for (int j = 0; j < 4; j++) wmma::fill_fragment(acc[i][j], 0.f);

#pragma unroll
    for (int i = 0; i < STAGES - 1; i++) { issue(i); cp_commit(); }

    for (int g = 0; g < nk3; ++g) {
        cp_wait<STAGES - 2>();   // stage g resident
        __syncthreads();         // visibility; stage (g-1)%STAGES free for overwrite
        if (g + STAGES - 1 < nk3) issue(g + STAGES - 1);
        cp_commit();             // unconditional: uniform group accounting at tail
        const int s = g % STAGES;
        const __half* Ab = sA + s * A_STAGE + (w_m * 32) * LDA;
        const __half* Bb = sB + s * B_STAGE + w_n * 64;
#pragma unroll
        for (int kk = 0; kk < 2; kk++) {
            wmma::fragment<wmma::matrix_a, 16, 16, 16, __half, wmma::row_major> af[2];
            wmma::fragment<wmma::matrix_b, 16, 16, 16, __half, wmma::row_major> bf[4];
#pragma unroll
            for (int i = 0; i < 2; i++)
                wmma::load_matrix_sync(af[i], Ab + i * 16 * LDA + kk * 16, LDA);
#pragma unroll
            for (int j = 0; j < 4; j++)
                wmma::load_matrix_sync(bf[j], Bb + kk * 16 * LDB + j * 16, LDB);
#pragma unroll
            for (int i = 0; i < 2; i++)
#pragma unroll
                for (int j = 0; j < 4; j++)
                    wmma::mma_sync(acc[i][j], af[i], bf[j], acc[i][j]);
        }
    }

    // epilogue: bias + relu + split fp16 (hi,lo), vectorized 16B stores
    __syncthreads();
    float* stage = (float*)smem_raw + wid * 256;           // 1KB/warp, reuses pipeline smem
    const int r = lane >> 1, c0 = (lane & 1) * 8;
#pragma unroll
    for (int i = 0; i < 2; i++) {
#pragma unroll
        for (int j = 0; j < 4; j++) {
            wmma::store_matrix_sync(stage, acc[i][j], 16, wmma::mem_row_major);
            __syncwarp();
            union { uint4 u; __half h[8]; } ph, pl;
#pragma unroll
            for (int e = 0; e < 8; e++) {
                float v = fmaxf(stage[r * 16 + c0 + e] + sBias[w_n * 64 + j * 16 + c0 + e], 0.f);
                __half hh = __float2half_rn(v);
                ph.h[e] = hh;
                pl.h[e] = __float2half_rn(v - __half2float(hh));
            }
            size_t base = (size_t)(m0 + w_m * 32 + i * 16 + r) * 256
                        + n0 + w_n * 64 + j * 16 + c0;
            *(uint4*)(outh + base) = ph.u;
            *(uint4*)(outl + base) = pl.u;
            __syncwarp();
        }
    }
}

// ---------------- conv4 (3x3, 256->1) + sigmoid: 64 pixels/block, warp per pixel ----------
__global__ void __launch_bounds__(256) conv4_kernel(const float* __restrict__ b4,
                                                    float* __restrict__ extra)
{
    __shared__ float sw[9 * NCH];
    for (int i = threadIdx.x; i < 9 * NCH; i += 256) sw[i] = g_w4c[i];
    __syncthreads();

    int wid = threadIdx.x >> 5, lane = threadIdx.x & 31;
    int pix0 = blockIdx.x * 64 + wid * 8;
    float bb = b4[0];
#pragma unroll
    for (int t = 0; t < 8; t++) {
        int gw = pix0 + t;
        int b = gw >> 16, y = (gw >> 8) & 255, xx = gw & 255;
        float acc = 0.f;
#pragma unroll
        for (int tap = 0; tap < 9; tap++) {
            int dy = tap / 3 - 1, dx = tap % 3 - 1;
            int src = (b << 16) | (((y + dy) & 255) << 8) | ((xx + dx) & 255);
            union { uint4 u; __half2 h[4]; } vh, vl;
            vh.u = *(const uint4*)(g_h3h + (size_t)src * 256 + lane * 8);
            vl.u = *(const uint4*)(g_h3l + (size_t)src * 256 + lane * 8);
            const float* wt = sw + tap * 256 + lane * 8;
#pragma unroll
            for (int e = 0; e < 4; e++) {
                float2 fh = __half22float2(vh.h[e]);
                float2 fl = __half22float2(vl.h[e]);
                acc += (fh.x + fl.x) * wt[2 * e] + (fh.y + fl.y) * wt[2 * e + 1];
            }
        }
#pragma unroll
        for (int o = 16; o; o >>= 1) acc += __shfl_xor_sync(0xffffffffu, acc, o);
        if (lane == 0) {
            float rr = 1.f / (1.f + expf(-(acc + bb)));
            g_xp[gw] = rr;
            if (extra) extra[gw] = rr;
        }
    }
}

// ---------------- launch ----------------
extern "C" void kernel_launch(void* const* d_in, const int* in_sizes, int n_in,
                              void* d_out, int out_size)
{
    const float* x  = (const float*)d_in[0];
    const float* w1 = (const float*)d_in[1];
    const float* b1 = (const float*)d_in[2];
    const float* w2 = (const float*)d_in[3];
    const float* b2 = (const float*)d_in[4];
    const float* w3 = (const float*)d_in[5];
    const float* b3 = (const float*)d_in[6];
    const float* w4 = (const float*)d_in[7];
    const float* b4 = (const float*)d_in[8];
    float* out = (float*)d_out;

    void *pFh, *pFl, *ph1h, *ph1l, *ph2h, *ph2l, *ph3h, *ph3l;
    void *pW1h, *pW1l, *pW2h, *pW2l, *pW3h, *pW3l, *pxp;
    cudaGetSymbolAddress(&pFh, g_Fh);   cudaGetSymbolAddress(&pFl, g_Fl);
    cudaGetSymbolAddress(&ph1h, g_h1h); cudaGetSymbolAddress(&ph1l, g_h1l);
    cudaGetSymbolAddress(&ph2h, g_h2h); cudaGetSymbolAddress(&ph2l, g_h2l);
    cudaGetSymbolAddress(&ph3h, g_h3h); cudaGetSymbolAddress(&ph3l, g_h3l);
    cudaGetSymbolAddress(&pW1h, g_W1h); cudaGetSymbolAddress(&pW1l, g_W1l);
    cudaGetSymbolAddress(&pW2h, g_W2h); cudaGetSymbolAddress(&pW2l, g_W2l);
    cudaGetSymbolAddress(&pW3h, g_W3h); cudaGetSymbolAddress(&pW3l, g_W3l);
    cudaGetSymbolAddress(&pxp, g_xp);

    cudaFuncSetAttribute(gemm_kernel, cudaFuncAttributeMaxDynamicSharedMemorySize, SMEM_BYTES);

    // xp <- x
    cudaMemcpyAsync(pxp, x, (size_t)MTOT * sizeof(float), cudaMemcpyDeviceToDevice, 0);

    prep_weights<<<2304, 256>>>(w1, w2, w3, w4);

    dim3 ggrid(2, MTOT / 128);
    for (int it = 0; it < N_IT; ++it) {
        features_kernel<<<MTOT / 256, 256>>>(x);
        gemm_kernel<<<ggrid, 256, SMEM_BYTES>>>((const __half*)pFh, (const __half*)pFl,
                                                (const __half*)pW1h, (const __half*)pW1l, b1,
                                                (__half*)ph1h, (__half*)ph1l, K1P, 2);
        gemm_kernel<<<ggrid, 256, SMEM_BYTES>>>((const __half*)ph1h, (const __half*)ph1l,
                                                (const __half*)pW2h, (const __half*)pW2l, b2,
                                                (__half*)ph2h, (__half*)ph2l, K2, 1);
        gemm_kernel<<<ggrid, 256, SMEM_BYTES>>>((const __half*)ph2h, (const __half*)ph2l,
                                                (const __half*)pW3h, (const __half*)pW3l, b3,
                                                (__half*)ph3h, (__half*)ph3l, K3, 0);
        conv4_kernel<<<MTOT / 64, 256>>>(b4, (it == N_IT - 1) ? out : nullptr);
    }
}